// round 2
// baseline (speedup 1.0000x reference)
#include <cuda_runtime.h>
#include <math.h>

#define N_NODES 25000
#define N_EDGES 400000
#define HIDDEN  128
#define NUM_RBF 50
#define CUTOFF_R 10.0f

// Output layout (floats), concatenated in reference return order:
// h_updated, v_updated, f_updated, angular_info, dihedral_info, direction_units
#define O_H   0
#define O_V   3200000
#define O_F   12800000
#define O_ANG 64000000
#define O_DIH 67200000
#define O_DU  118400000

// ---------------- scratch (static device memory; no allocations) ----------------
__device__ float g_unit[3][N_EDGES];          // unit vectors (planar)
__device__ float g_cw[N_EDGES];               // cutoff weights
__device__ float g_hA[N_NODES * HIDDEN];      // h @ W_msg[0:128]   (gathered at col)
__device__ float g_hB[N_NODES * HIDDEN];      // h @ W_msg[128:256] (gathered at row)
__device__ float g_s[N_EDGES * HIDDEN];       // scalar_msg
__device__ float g_w[N_EDGES * 2 * HIDDEN];   // vec_weights (w1 | w2)
__device__ float g_csA[HIDDEN];               // colsum(W_ang)
__device__ float g_csD[HIDDEN];               // colsum(W_dih)

__device__ __forceinline__ float sigmoidf_(float x) {
    return 1.0f / (1.0f + expf(-x));
}

// ---------------- K1: colsums of W_ang / W_dih ----------------
__global__ void k_prep(const float* __restrict__ W_ang, const float* __restrict__ W_dih) {
    int k = threadIdx.x;
    float a = 0.f, d = 0.f;
    #pragma unroll 8
    for (int j = 0; j < HIDDEN; j++) {
        a += W_ang[j * HIDDEN + k];
        d += W_dih[j * HIDDEN + k];
    }
    g_csA[k] = a;
    g_csD[k] = d;
}

// ---------------- K2: zero direction_units region ----------------
__global__ void k_zero_du(float* __restrict__ du) {
    int i = blockIdx.x * blockDim.x + threadIdx.x;
    if (i < N_NODES * 3) du[i] = 0.0f;
}

// ---------------- K3: edge geometry + direction_units scatter ----------------
__global__ void k_geom(const float* __restrict__ pos, const int* __restrict__ ei,
                       float* __restrict__ du) {
    int e = blockIdx.x * blockDim.x + threadIdx.x;
    if (e >= N_EDGES) return;
    int r = ei[e];
    int c = ei[N_EDGES + e];
    float dx = pos[c * 3 + 0] - pos[r * 3 + 0];
    float dy = pos[c * 3 + 1] - pos[r * 3 + 1];
    float dz = pos[c * 3 + 2] - pos[r * 3 + 2];
    float dist = sqrtf(dx * dx + dy * dy + dz * dz) + 1e-8f;
    float inv = 1.0f / dist;
    float ux = dx * inv, uy = dy * inv, uz = dz * inv;
    g_unit[0][e] = ux; g_unit[1][e] = uy; g_unit[2][e] = uz;
    float cw = (dist < CUTOFF_R)
             ? 0.5f * (cosf(3.14159265358979323846f * dist / CUTOFF_R) + 1.0f)
             : 0.0f;
    g_cw[e] = cw;
    atomicAdd(&du[r * 3 + 0],  ux);
    atomicAdd(&du[r * 3 + 1],  uy);
    atomicAdd(&du[r * 3 + 2],  uz);
    atomicAdd(&du[c * 3 + 0], -ux);
    atomicAdd(&du[c * 3 + 1], -uy);
    atomicAdd(&du[c * 3 + 2], -uz);
}

// ---------------- K4: per-node — g_hA/g_hB, angular gate, h_updated, angular_info ----------------
// 8 nodes per block, 128 threads; thread k owns output column k.
__global__ void k_node(const float* __restrict__ h,
                       const float* __restrict__ W_msg,
                       const float* __restrict__ W_scalar,
                       const float* __restrict__ b_scalar,
                       const float* __restrict__ b_ang,
                       const float* __restrict__ du,
                       float* __restrict__ out) {
    int n0 = blockIdx.x * 8;
    int k = threadIdx.x;
    __shared__ float hs[8][HIDDEN];
    __shared__ float angs[8];
    #pragma unroll
    for (int i = 0; i < 8; i++) hs[i][k] = h[(n0 + i) * HIDDEN + k];
    if (k < 8) {
        int n = n0 + k;
        float x = du[n * 3 + 0], y = du[n * 3 + 1], z = du[n * 3 + 2];
        angs[k] = x * x + y * y + z * z;
    }
    __syncthreads();

    float accA[8], accB[8], accS[8];
    #pragma unroll
    for (int i = 0; i < 8; i++) { accA[i] = 0.f; accB[i] = 0.f; accS[i] = 0.f; }

    for (int j = 0; j < HIDDEN; j++) {
        float wA = W_msg[j * HIDDEN + k];             // rows 0..127   -> h[col] part
        float wB = W_msg[(HIDDEN + j) * HIDDEN + k];  // rows 128..255 -> h[row] part
        float wS = W_scalar[j * HIDDEN + k];
        #pragma unroll
        for (int i = 0; i < 8; i++) {
            float hv = hs[i][j];
            accA[i] += hv * wA;
            accB[i] += hv * wB;
            accS[i] += hv * wS;
        }
    }

    float csA = g_csA[k], ba = b_ang[k], bs = b_scalar[k];
    #pragma unroll
    for (int i = 0; i < 8; i++) {
        int n = n0 + i;
        g_hA[n * HIDDEN + k] = accA[i];
        g_hB[n * HIDDEN + k] = accB[i];
        float ang  = angs[i];
        float gate = sigmoidf_(ang * csA + ba);
        out[O_H   + n * HIDDEN + k] = hs[i][k] + (accS[i] + bs) * gate;
        out[O_ANG + n * HIDDEN + k] = ang;
    }
}

// ---------------- K5: scalar_msg = g_hA[col] + g_hB[row] + rbf @ W_rbf + b_msg ----------------
// 8 edges per block, 128 threads.
__global__ void k_smsg(const float* __restrict__ rbf, const int* __restrict__ ei,
                       const float* __restrict__ W_msg, const float* __restrict__ b_msg) {
    int e0 = blockIdx.x * 8;
    int k = threadIdx.x;
    __shared__ float rs[8][NUM_RBF];
    __shared__ int rows[8], cols[8];
    for (int t = k; t < 8 * NUM_RBF; t += 128) {
        int i = t / NUM_RBF, r = t % NUM_RBF;
        rs[i][r] = rbf[(e0 + i) * NUM_RBF + r];
    }
    if (k < 8) { rows[k] = ei[e0 + k]; cols[k] = ei[N_EDGES + e0 + k]; }
    __syncthreads();

    float b = b_msg[k];
    float acc[8];
    #pragma unroll
    for (int i = 0; i < 8; i++) acc[i] = b;

    for (int r = 0; r < NUM_RBF; r++) {
        float w = W_msg[(2 * HIDDEN + r) * HIDDEN + k];  // rows 256..305 -> rbf part
        #pragma unroll
        for (int i = 0; i < 8; i++) acc[i] += rs[i][r] * w;
    }
    #pragma unroll
    for (int i = 0; i < 8; i++) {
        acc[i] += g_hA[cols[i] * HIDDEN + k] + g_hB[rows[i] * HIDDEN + k];
        g_s[(e0 + i) * HIDDEN + k] = acc[i];
    }
}

// ---------------- K6: vec_weights = scalar_msg @ W_vec + b_vec ----------------
// 16 edges per block, 128 threads; thread k owns w1[k] and w2[k] (2 outputs).
__global__ void k_vec(const float* __restrict__ W_vec, const float* __restrict__ b_vec) {
    int e0 = blockIdx.x * 16;
    int k = threadIdx.x;
    __shared__ float ss[16][HIDDEN];
    for (int t = k; t < 16 * HIDDEN; t += 128) {
        ss[t >> 7][t & 127] = g_s[e0 * HIDDEN + t];
    }
    __syncthreads();

    float b1 = b_vec[k], b2 = b_vec[HIDDEN + k];
    float a1[16], a2[16];
    #pragma unroll
    for (int i = 0; i < 16; i++) { a1[i] = b1; a2[i] = b2; }

    for (int j = 0; j < HIDDEN; j++) {
        float w1 = W_vec[j * 2 * HIDDEN + k];
        float w2 = W_vec[j * 2 * HIDDEN + HIDDEN + k];
        #pragma unroll
        for (int i = 0; i < 16; i++) {
            float s = ss[i][j];
            a1[i] += s * w1;
            a2[i] += s * w2;
        }
    }
    #pragma unroll
    for (int i = 0; i < 16; i++) {
        g_w[(e0 + i) * 2 * HIDDEN + k]          = a1[i];
        g_w[(e0 + i) * 2 * HIDDEN + HIDDEN + k] = a2[i];
    }
}

// ---------------- K7: vec_msg scatter-add into v_updated (float4 REDs) ----------------
// one edge per block, 128 threads.
__global__ void k_scatter(const float* __restrict__ v, const int* __restrict__ ei,
                          float* __restrict__ out_v) {
    int e = blockIdx.x;
    int k = threadIdx.x;
    __shared__ float m[3 * HIDDEN];
    int r = ei[e];
    int c = ei[N_EDGES + e];
    float cw = g_cw[e];
    float ux = g_unit[0][e], uy = g_unit[1][e], uz = g_unit[2][e];
    float w1 = g_w[e * 2 * HIDDEN + k] * cw;
    float w2 = g_w[e * 2 * HIDDEN + HIDDEN + k] * cw;
    const float* vr = v + (size_t)r * 3 * HIDDEN;
    m[k]              = w1 * ux + w2 * vr[k];
    m[HIDDEN + k]     = w1 * uy + w2 * vr[HIDDEN + k];
    m[2 * HIDDEN + k] = w1 * uz + w2 * vr[2 * HIDDEN + k];
    __syncthreads();
    if (k < 96) {
        float4 val = *reinterpret_cast<float4*>(&m[k * 4]);
        atomicAdd(reinterpret_cast<float4*>(out_v + (size_t)c * 3 * HIDDEN + k * 4), val);
    }
}

// ---------------- K8: dihedral + f gating + dihedral_info ----------------
// 16 edges per block, 128 threads.
__global__ void k_fgate(const float* __restrict__ f, const int* __restrict__ ei,
                        const float* __restrict__ W_edge, const float* __restrict__ b_edge,
                        const float* __restrict__ b_dih, const float* __restrict__ du,
                        float* __restrict__ out) {
    int e0 = blockIdx.x * 16;
    int k = threadIdx.x;
    __shared__ float fs[16][HIDDEN];
    __shared__ float dihs[16];
    for (int t = k; t < 16 * HIDDEN; t += 128) {
        fs[t >> 7][t & 127] = f[(size_t)e0 * HIDDEN + t];
    }
    if (k < 16) {
        int e = e0 + k;
        int r = ei[e], c = ei[N_EDGES + e];
        float ux = g_unit[0][e], uy = g_unit[1][e], uz = g_unit[2][e];
        float vix = du[r * 3 + 0], viy = du[r * 3 + 1], viz = du[r * 3 + 2];
        float vjx = du[c * 3 + 0], vjy = du[c * 3 + 1], vjz = du[c * 3 + 2];
        float di = vix * ux + viy * uy + viz * uz;
        float dj = vjx * ux + vjy * uy + vjz * uz;
        float ax = vix - di * ux, ay = viy - di * uy, az = viz - di * uz;
        float bx = vjx - dj * ux, by = vjy - dj * uy, bz = vjz - dj * uz;
        dihs[k] = ax * bx + ay * by + az * bz;
    }
    __syncthreads();

    float acc[16];
    #pragma unroll
    for (int i = 0; i < 16; i++) acc[i] = 0.f;

    for (int j = 0; j < HIDDEN; j++) {
        float w = W_edge[j * HIDDEN + k];
        #pragma unroll
        for (int i = 0; i < 16; i++) acc[i] += fs[i][j] * w;
    }

    float csD = g_csD[k], bd = b_dih[k], be = b_edge[k];
    #pragma unroll
    for (int i = 0; i < 16; i++) {
        float dih  = dihs[i];
        float gate = sigmoidf_(dih * csD + bd);
        int e = e0 + i;
        out[O_F   + e * HIDDEN + k] = fs[i][k] + (acc[i] + be) * gate;
        out[O_DIH + e * HIDDEN + k] = dih;
    }
}

// ---------------- launch ----------------
extern "C" void kernel_launch(void* const* d_in, const int* in_sizes, int n_in,
                              void* d_out, int out_size) {
    const float* h        = (const float*)d_in[0];
    const float* v        = (const float*)d_in[1];
    const float* f        = (const float*)d_in[2];
    const float* pos      = (const float*)d_in[3];
    const float* edge_rbf = (const float*)d_in[4];
    const int*   ei       = (const int*)  d_in[5];
    const float* W_msg    = (const float*)d_in[6];
    const float* b_msg    = (const float*)d_in[7];
    const float* W_vec    = (const float*)d_in[8];
    const float* b_vec    = (const float*)d_in[9];
    const float* W_scalar = (const float*)d_in[10];
    const float* b_scalar = (const float*)d_in[11];
    const float* W_edge   = (const float*)d_in[12];
    const float* b_edge   = (const float*)d_in[13];
    const float* W_ang    = (const float*)d_in[14];
    const float* b_ang    = (const float*)d_in[15];
    const float* W_dih    = (const float*)d_in[16];
    const float* b_dih    = (const float*)d_in[17];
    float* out = (float*)d_out;

    // v_updated starts as a copy of v (atomics accumulate on top)
    cudaMemcpyAsync(out + O_V, v, (size_t)N_NODES * 3 * HIDDEN * sizeof(float),
                    cudaMemcpyDeviceToDevice, 0);

    k_prep<<<1, HIDDEN>>>(W_ang, W_dih);
    k_zero_du<<<(N_NODES * 3 + 255) / 256, 256>>>(out + O_DU);
    k_geom<<<(N_EDGES + 255) / 256, 256>>>(pos, ei, out + O_DU);
    k_node<<<N_NODES / 8, HIDDEN>>>(h, W_msg, W_scalar, b_scalar, b_ang, out + O_DU, out);
    k_smsg<<<N_EDGES / 8, HIDDEN>>>(edge_rbf, ei, W_msg, b_msg);
    k_vec<<<N_EDGES / 16, HIDDEN>>>(W_vec, b_vec);
    k_scatter<<<N_EDGES, HIDDEN>>>(v, ei, out + O_V);
    k_fgate<<<N_EDGES / 16, HIDDEN>>>(f, ei, W_edge, b_edge, b_dih, out + O_DU, out);
}

// round 4
// speedup vs baseline: 1.4644x; 1.4644x over previous
#include <cuda_runtime.h>
#include <math.h>

#define N_NODES 25000
#define N_EDGES 400000
#define HIDDEN  128
#define NUM_RBF 50
#define CUTOFF_R 10.0f

// Output layout (floats): h_updated, v_updated, f_updated, angular_info, dihedral_info, direction_units
#define O_H   0
#define O_V   3200000
#define O_F   12800000
#define O_ANG 64000000
#define O_DIH 67200000
#define O_DU  118400000

// ---------------- scratch ----------------
__device__ float g_unit[3][N_EDGES];
__device__ float g_cw[N_EDGES];
__device__ float g_hAV[N_NODES * 256];   // h @ (W_msgA @ W_vec)  (gathered at col)
__device__ float g_hBV[N_NODES * 256];   // h @ (W_msgB @ W_vec)  (gathered at row)
__device__ float g_WAV[128 * 256];
__device__ float g_WBV[128 * 256];
__device__ float g_WRV[NUM_RBF * 256];
__device__ float g_bV[256];              // b_msg @ W_vec + b_vec
__device__ float g_csA[HIDDEN];
__device__ float g_csD[HIDDEN];

__device__ __forceinline__ float sigmoidf_(float x) { return 1.0f / (1.0f + expf(-x)); }

// ---------------- K1: colsums + fused bias ----------------
__global__ void k_prep(const float* __restrict__ W_ang, const float* __restrict__ W_dih,
                       const float* __restrict__ b_msg, const float* __restrict__ W_vec,
                       const float* __restrict__ b_vec) {
    int k = threadIdx.x;  // 256 threads
    if (k < HIDDEN) {
        float a = 0.f, d = 0.f;
        #pragma unroll 8
        for (int j = 0; j < HIDDEN; j++) {
            a += W_ang[j * HIDDEN + k];
            d += W_dih[j * HIDDEN + k];
        }
        g_csA[k] = a; g_csD[k] = d;
    }
    float b = 0.f;
    #pragma unroll 8
    for (int j = 0; j < HIDDEN; j++) b += b_msg[j] * W_vec[j * 256 + k];
    g_bV[k] = b + b_vec[k];
}

// ---------------- K1b: combined weight products W_msg(306x128) @ W_vec(128x256) ----------------
__global__ void k_prepW(const float* __restrict__ W_msg, const float* __restrict__ W_vec) {
    int r = blockIdx.x;   // 306 rows
    int k = threadIdx.x;  // 128 threads, each does cols k and k+128
    __shared__ float wr[HIDDEN];
    wr[k] = W_msg[r * HIDDEN + k];
    __syncthreads();
    float a = 0.f, b = 0.f;
    #pragma unroll 4
    for (int t = 0; t < HIDDEN; t++) {
        float w = wr[t];
        a += w * W_vec[t * 256 + k];
        b += w * W_vec[t * 256 + 128 + k];
    }
    float* dst = (r < 128) ? &g_WAV[r * 256]
               : (r < 256) ? &g_WBV[(r - 128) * 256]
                           : &g_WRV[(r - 256) * 256];
    dst[k] = a; dst[128 + k] = b;
}

// ---------------- K2: zero direction_units ----------------
__global__ void k_zero_du(float* __restrict__ du) {
    int i = blockIdx.x * blockDim.x + threadIdx.x;
    if (i < N_NODES * 3) du[i] = 0.0f;
}

// ---------------- K3: edge geometry + direction_units scatter ----------------
__global__ void k_geom(const float* __restrict__ pos, const int* __restrict__ ei,
                       float* __restrict__ du) {
    int e = blockIdx.x * blockDim.x + threadIdx.x;
    if (e >= N_EDGES) return;
    int r = ei[e];
    int c = ei[N_EDGES + e];
    float dx = pos[c * 3 + 0] - pos[r * 3 + 0];
    float dy = pos[c * 3 + 1] - pos[r * 3 + 1];
    float dz = pos[c * 3 + 2] - pos[r * 3 + 2];
    float dist = sqrtf(dx * dx + dy * dy + dz * dz) + 1e-8f;
    float inv = 1.0f / dist;
    float ux = dx * inv, uy = dy * inv, uz = dz * inv;
    g_unit[0][e] = ux; g_unit[1][e] = uy; g_unit[2][e] = uz;
    float cw = (dist < CUTOFF_R)
             ? 0.5f * (cosf(3.14159265358979323846f * dist / CUTOFF_R) + 1.0f)
             : 0.0f;
    g_cw[e] = cw;
    atomicAdd(&du[r * 3 + 0],  ux);
    atomicAdd(&du[r * 3 + 1],  uy);
    atomicAdd(&du[r * 3 + 2],  uz);
    atomicAdd(&du[c * 3 + 0], -ux);
    atomicAdd(&du[c * 3 + 1], -uy);
    atomicAdd(&du[c * 3 + 2], -uz);
}

// ---------------- K4: per-node — hAV, hBV, h_updated, angular_info ----------------
// 8 nodes per block, 128 threads. Activations j-major in smem, read as float4.
__global__ void __launch_bounds__(128) k_node(
        const float* __restrict__ h,
        const float* __restrict__ W_scalar,
        const float* __restrict__ b_scalar,
        const float* __restrict__ b_ang,
        const float* __restrict__ du,
        float* __restrict__ out) {
    int n0 = blockIdx.x * 8;           // N_NODES % 8 == 0
    int k = threadIdx.x;
    __shared__ __align__(16) float hs[HIDDEN][8];   // [j][node]
    __shared__ float angs[8];
    #pragma unroll
    for (int i = 0; i < 8; i++) hs[k][i] = h[(size_t)(n0 + i) * HIDDEN + k];
    if (k < 8) {
        int n = n0 + k;
        float x = du[n * 3 + 0], y = du[n * 3 + 1], z = du[n * 3 + 2];
        angs[k] = x * x + y * y + z * z;
    }
    __syncthreads();

    float aA1[8], aA2[8], aB1[8], aB2[8], aS[8];
    #pragma unroll
    for (int i = 0; i < 8; i++) { aA1[i]=0.f; aA2[i]=0.f; aB1[i]=0.f; aB2[i]=0.f; aS[i]=0.f; }

    #pragma unroll 2
    for (int j = 0; j < HIDDEN; j++) {
        float wA1 = g_WAV[j * 256 + k];
        float wA2 = g_WAV[j * 256 + 128 + k];
        float wB1 = g_WBV[j * 256 + k];
        float wB2 = g_WBV[j * 256 + 128 + k];
        float wS  = W_scalar[j * HIDDEN + k];
        float4 sa = *reinterpret_cast<const float4*>(&hs[j][0]);
        float4 sb = *reinterpret_cast<const float4*>(&hs[j][4]);
        float s[8] = {sa.x, sa.y, sa.z, sa.w, sb.x, sb.y, sb.z, sb.w};
        #pragma unroll
        for (int i = 0; i < 8; i++) {
            aA1[i] = fmaf(s[i], wA1, aA1[i]);
            aA2[i] = fmaf(s[i], wA2, aA2[i]);
            aB1[i] = fmaf(s[i], wB1, aB1[i]);
            aB2[i] = fmaf(s[i], wB2, aB2[i]);
            aS[i]  = fmaf(s[i], wS,  aS[i]);
        }
    }

    float csA = g_csA[k], ba = b_ang[k], bs = b_scalar[k];
    #pragma unroll
    for (int i = 0; i < 8; i++) {
        int n = n0 + i;
        g_hAV[(size_t)n * 256 + k]       = aA1[i];
        g_hAV[(size_t)n * 256 + 128 + k] = aA2[i];
        g_hBV[(size_t)n * 256 + k]       = aB1[i];
        g_hBV[(size_t)n * 256 + 128 + k] = aB2[i];
        float ang  = angs[i];
        float gate = sigmoidf_(ang * csA + ba);
        out[O_H   + (size_t)n * HIDDEN + k] = hs[k][i] + (aS[i] + bs) * gate;
        out[O_ANG + (size_t)n * HIDDEN + k] = ang;
    }
}

// ---------------- K5: fused vec path — rbf mini-GEMM + gathers + vec_msg scatter ----------------
// 16 edges per block, 128 threads.
__global__ void __launch_bounds__(128) k_edge(
        const float* __restrict__ v, const int* __restrict__ ei,
        const float* __restrict__ rbf, float* __restrict__ out_v) {
    const int EB = 16;
    int e0 = blockIdx.x * EB;          // N_EDGES % 16 == 0
    int k = threadIdx.x;
    __shared__ __align__(16) float rs[NUM_RBF][EB];     // [rbf][edge]
    __shared__ __align__(16) float m[EB][3 * HIDDEN];   // messages
    __shared__ float s_u[3][EB], s_cw[EB];
    __shared__ int s_row[EB], s_col[EB];

    for (int t = k; t < EB * NUM_RBF; t += 128) {
        int i = t / NUM_RBF, r = t - i * NUM_RBF;       // coalesced global reads per edge
        rs[r][i] = rbf[(size_t)(e0 + i) * NUM_RBF + r];
    }
    if (k < EB) {
        int e = e0 + k;
        s_row[k] = ei[e]; s_col[k] = ei[N_EDGES + e];
        s_u[0][k] = g_unit[0][e]; s_u[1][k] = g_unit[1][e]; s_u[2][k] = g_unit[2][e];
        s_cw[k] = g_cw[e];
    }
    __syncthreads();

    float a1[EB], a2[EB];
    #pragma unroll
    for (int i = 0; i < EB; i++) { a1[i] = 0.f; a2[i] = 0.f; }

    #pragma unroll 2
    for (int r = 0; r < NUM_RBF; r++) {
        float w1 = g_WRV[r * 256 + k];
        float w2 = g_WRV[r * 256 + 128 + k];
        #pragma unroll
        for (int q = 0; q < EB / 4; q++) {
            float4 s4 = *reinterpret_cast<const float4*>(&rs[r][4 * q]);
            float s[4] = {s4.x, s4.y, s4.z, s4.w};
            #pragma unroll
            for (int l = 0; l < 4; l++) {
                a1[4 * q + l] = fmaf(s[l], w1, a1[4 * q + l]);
                a2[4 * q + l] = fmaf(s[l], w2, a2[4 * q + l]);
            }
        }
    }

    float bV1 = g_bV[k], bV2 = g_bV[128 + k];

    #pragma unroll 4
    for (int i = 0; i < EB; i++) {
        int r_ = s_row[i], c_ = s_col[i];
        float cw = s_cw[i];
        float w1 = (a1[i] + g_hAV[(size_t)c_ * 256 + k]
                          + g_hBV[(size_t)r_ * 256 + k] + bV1) * cw;
        float w2 = (a2[i] + g_hAV[(size_t)c_ * 256 + 128 + k]
                          + g_hBV[(size_t)r_ * 256 + 128 + k] + bV2) * cw;
        const float* vr = v + (size_t)r_ * 3 * HIDDEN;
        m[i][k]              = w1 * s_u[0][i] + w2 * vr[k];
        m[i][HIDDEN + k]     = w1 * s_u[1][i] + w2 * vr[HIDDEN + k];
        m[i][2 * HIDDEN + k] = w1 * s_u[2][i] + w2 * vr[2 * HIDDEN + k];
    }
    __syncthreads();

    for (int t = k; t < EB * 96; t += 128) {
        int i = t / 96, q = t - i * 96;
        float4 val = *reinterpret_cast<float4*>(&m[i][q * 4]);
        int c_ = s_col[i];
        atomicAdd(reinterpret_cast<float4*>(out_v + (size_t)c_ * 3 * HIDDEN + q * 4), val);
    }
}

// ---------------- K6: dihedral + f gating — 32 edges/block ----------------
__global__ void __launch_bounds__(128) k_fgate(
        const float* __restrict__ f, const int* __restrict__ ei,
        const float* __restrict__ W_edge, const float* __restrict__ b_edge,
        const float* __restrict__ b_dih, const float* __restrict__ du,
        float* __restrict__ out) {
    int e0 = blockIdx.x * 32;          // N_EDGES % 32 == 0
    int k = threadIdx.x;
    __shared__ __align__(16) float fs[HIDDEN][32];   // [j][edge]
    __shared__ float dihs[32];
    #pragma unroll
    for (int i = 0; i < 32; i++) fs[k][i] = f[(size_t)(e0 + i) * HIDDEN + k];
    if (k < 32) {
        int e = e0 + k;
        int r = ei[e], c = ei[N_EDGES + e];
        float ux = g_unit[0][e], uy = g_unit[1][e], uz = g_unit[2][e];
        float vix = du[r * 3 + 0], viy = du[r * 3 + 1], viz = du[r * 3 + 2];
        float vjx = du[c * 3 + 0], vjy = du[c * 3 + 1], vjz = du[c * 3 + 2];
        float di = vix * ux + viy * uy + viz * uz;
        float dj = vjx * ux + vjy * uy + vjz * uz;
        float ax = vix - di * ux, ay = viy - di * uy, az = viz - di * uz;
        float bx = vjx - dj * ux, by = vjy - dj * uy, bz = vjz - dj * uz;
        dihs[k] = ax * bx + ay * by + az * bz;
    }
    __syncthreads();

    float acc[32];
    #pragma unroll
    for (int i = 0; i < 32; i++) acc[i] = 0.f;

    #pragma unroll 2
    for (int j = 0; j < HIDDEN; j++) {
        float w = W_edge[j * HIDDEN + k];
        #pragma unroll
        for (int q = 0; q < 8; q++) {
            float4 s4 = *reinterpret_cast<const float4*>(&fs[j][4 * q]);
            float s[4] = {s4.x, s4.y, s4.z, s4.w};
            #pragma unroll
            for (int l = 0; l < 4; l++)
                acc[4 * q + l] = fmaf(s[l], w, acc[4 * q + l]);
        }
    }

    float csD = g_csD[k], bd = b_dih[k], be = b_edge[k];
    #pragma unroll
    for (int i = 0; i < 32; i++) {
        size_t e = (size_t)e0 + i;
        float dih  = dihs[i];
        float gate = sigmoidf_(dih * csD + bd);
        out[O_F   + e * HIDDEN + k] = fs[k][i] + (acc[i] + be) * gate;
        out[O_DIH + e * HIDDEN + k] = dih;
    }
}

// ---------------- launch ----------------
extern "C" void kernel_launch(void* const* d_in, const int* in_sizes, int n_in,
                              void* d_out, int out_size) {
    const float* h        = (const float*)d_in[0];
    const float* v        = (const float*)d_in[1];
    const float* f        = (const float*)d_in[2];
    const float* pos      = (const float*)d_in[3];
    const float* edge_rbf = (const float*)d_in[4];
    const int*   ei       = (const int*)  d_in[5];
    const float* W_msg    = (const float*)d_in[6];
    const float* b_msg    = (const float*)d_in[7];
    const float* W_vec    = (const float*)d_in[8];
    const float* b_vec    = (const float*)d_in[9];
    const float* W_scalar = (const float*)d_in[10];
    const float* b_scalar = (const float*)d_in[11];
    const float* W_edge   = (const float*)d_in[12];
    const float* b_edge   = (const float*)d_in[13];
    const float* W_ang    = (const float*)d_in[14];
    const float* b_ang    = (const float*)d_in[15];
    const float* W_dih    = (const float*)d_in[16];
    const float* b_dih    = (const float*)d_in[17];
    float* out = (float*)d_out;

    cudaMemcpyAsync(out + O_V, v, (size_t)N_NODES * 3 * HIDDEN * sizeof(float),
                    cudaMemcpyDeviceToDevice, 0);

    k_prep<<<1, 256>>>(W_ang, W_dih, b_msg, W_vec, b_vec);
    k_prepW<<<306, 128>>>(W_msg, W_vec);
    k_zero_du<<<(N_NODES * 3 + 255) / 256, 256>>>(out + O_DU);
    k_geom<<<(N_EDGES + 255) / 256, 256>>>(pos, ei, out + O_DU);
    k_node<<<N_NODES / 8, 128>>>(h, W_scalar, b_scalar, b_ang, out + O_DU, out);
    k_edge<<<N_EDGES / 16, 128>>>(v, ei, edge_rbf, out + O_V);
    k_fgate<<<N_EDGES / 32, 128>>>(f, ei, W_edge, b_edge, b_dih, out + O_DU, out);
}